// round 6
// baseline (speedup 1.0000x reference)
#include <cuda_runtime.h>
#include <math.h>
#include <stdint.h>

// ---------------- problem constants ----------------
#define BB   2
#define NN   2048
#define MM   64
#define CC   128
#define C2   256
#define BNR  4096                 // BB*NN rows
#define PCNT 262144               // BNR*MM pairwise positions
#define OUTC 64
#define EPS  1e-5f
#define SLOPE 0.2f
#define NPAIR 2048                // BNR/2 : one tile = 2 bn rows = 128 M-rows

// ---------------- device scratch ----------------
__device__ float g_P  [BNR*CC];          // point @ Wp^T
__device__ float g_Cc [BB*MM*CC];        // center @ Wc^T   [b][m][c]
__device__ float g_CcT[BB*CC*MM];        // transposed      [b][c][m]
// z2 stored [bn][m][o] : index = bn*16384 + m*256 + o   (256MB fp32)
__device__ float g_z2 [(size_t)PCNT*C2];
__device__ float g_zmax[BNR*C2];
__device__ float g_zmin[BNR*C2];
__device__ float g_z4 [BNR*128];
__device__ float g_z5 [BNR*OUTC];

__device__ float g_Sp[BB*CC], g_Sp2[BB*CC], g_Sc[BB*CC], g_Sc2[BB*CC];
__device__ float g_s2[C2], g_q2[C2];
__device__ float g_s3[C2], g_q3[C2], g_a3[C2], g_d3[C2];
__device__ float g_s4[128], g_q4[128], g_a4[128], g_d4[128];
__device__ float g_s5[OUTC], g_q5[OUTC], g_a5[OUTC], g_d5[OUTC];

// ---------------- helpers ----------------
__device__ __forceinline__ float to_tf32(float x) {
    uint32_t u;
    asm("cvt.rna.tf32.f32 %0, %1;" : "=r"(u) : "f"(x));
    return __uint_as_float(u);
}
__device__ __forceinline__ void mma_tf32(float* c,
        uint32_t a0, uint32_t a1, uint32_t a2, uint32_t a3,
        uint32_t b0, uint32_t b1) {
    asm volatile(
        "mma.sync.aligned.m16n8k8.row.col.f32.tf32.tf32.f32 "
        "{%0,%1,%2,%3}, {%4,%5,%6,%7}, {%8,%9}, {%0,%1,%2,%3};"
        : "+f"(c[0]), "+f"(c[1]), "+f"(c[2]), "+f"(c[3])
        : "r"(a0), "r"(a1), "r"(a2), "r"(a3), "r"(b0), "r"(b1));
}
__device__ __forceinline__ float lrelu(float x) { return (x >= 0.f) ? x : SLOPE * x; }

// ---------------- K0: zero accumulators ----------------
__global__ void rn_prep() {
    int t = threadIdx.x;                              // 256
    g_s2[t] = 0.f; g_q2[t] = 0.f; g_s3[t] = 0.f; g_q3[t] = 0.f;
    g_Sp[t] = 0.f; g_Sp2[t] = 0.f; g_Sc[t] = 0.f; g_Sc2[t] = 0.f;
    if (t < 128) { g_s4[t] = 0.f; g_q4[t] = 0.f; }
    if (t < OUTC) { g_s5[t] = 0.f; g_q5[t] = 0.f; }
}

// ---------------- K1: P = point@Wp^T ; Cc = center@Wc^T (+ transpose) ----------------
__global__ void rn_pc(const float* __restrict__ pf, const float* __restrict__ cf,
                      const float* __restrict__ W1) {
    __shared__ float sr[CC];
    int r = blockIdx.x, o = threadIdx.x;              // 128 threads
    if (r < BNR) {
        sr[o] = pf[r*CC + o];
        __syncthreads();
        const float* w = W1 + o*(2*CC);
        float acc = 0.f;
        #pragma unroll
        for (int c = 0; c < CC; c += 4) {
            float4 wv = *(const float4*)(w + c);
            acc = fmaf(wv.x, sr[c+0], acc); acc = fmaf(wv.y, sr[c+1], acc);
            acc = fmaf(wv.z, sr[c+2], acc); acc = fmaf(wv.w, sr[c+3], acc);
        }
        g_P[r*CC + o] = acc;
    } else {
        int rc = r - BNR;                             // 0..127
        sr[o] = cf[rc*CC + o];
        __syncthreads();
        const float* w = W1 + o*(2*CC) + CC;
        float acc = 0.f;
        #pragma unroll
        for (int c = 0; c < CC; c += 4) {
            float4 wv = *(const float4*)(w + c);
            acc = fmaf(wv.x, sr[c+0], acc); acc = fmaf(wv.y, sr[c+1], acc);
            acc = fmaf(wv.z, sr[c+2], acc); acc = fmaf(wv.w, sr[c+3], acc);
        }
        g_Cc[rc*CC + o] = acc;
        int b = rc >> 6, m = rc & 63;
        g_CcT[(b*128 + o)*64 + m] = acc;
    }
}

// ---------------- K2: partial sums for analytic bn1 stats ----------------
__global__ void rn_bn1a() {
    int b = blockIdx.x / 16, chunk = blockIdx.x % 16;
    int o = threadIdx.x;                              // 128
    float sp = 0.f, sp2 = 0.f;
    int n0 = chunk * 128;
    for (int n = n0; n < n0 + 128; n++) {
        float v = g_P[(b*NN + n)*CC + o];
        sp += v; sp2 = fmaf(v, v, sp2);
    }
    atomicAdd(&g_Sp [b*CC + o], sp);
    atomicAdd(&g_Sp2[b*CC + o], sp2);
    if (chunk == 0) {
        float sc = 0.f, sc2 = 0.f;
        for (int m = 0; m < MM; m++) {
            float v = g_Cc[(b*MM + m)*CC + o];
            sc += v; sc2 = fmaf(v, v, sc2);
        }
        g_Sc [b*CC + o] = sc;
        g_Sc2[b*CC + o] = sc2;
    }
}

// =====================================================================
// K3: passB : z2 = h1 @ W2^T -> direct frag store [bn][m][o] + bn2 stats
// smem floats: sW2 [256][132]=33792 | sA [k=128][m=128+8]=17408 | s2a/q2a 512
//              total 51712 floats = 206848 B
// =====================================================================
#define PB_PW 132
#define PB_PA 136
#define SMEM_PB (51712*4)
__global__ __launch_bounds__(256, 1) void rn_passB_mma(const float* __restrict__ W2,
                                                       const float* __restrict__ g1,
                                                       const float* __restrict__ b1) {
    extern __shared__ float sm[];
    float* sW2 = sm;                 // [o][k] pitch 132
    float* sA  = sW2 + 256*PB_PW;    // [k][m] pitch 136
    float* s2a = sA + 128*PB_PA;     // 256
    float* q2a = s2a + 256;          // 256
    __shared__ float sa1[128], sd1[128];

    int tid = threadIdx.x, wid = tid >> 5, lane = tid & 31;
    int g = lane >> 2, t = lane & 3;
    int wm = wid >> 2, wn = wid & 3;   // warp tile 64(M) x 64(N)

    // inline bn1 finalize (analytic stats)
    if (tid < 128) {
        float s = 0.f, q = 0.f;
        #pragma unroll
        for (int b = 0; b < BB; b++) {
            float sp = g_Sp[b*CC+tid], sp2 = g_Sp2[b*CC+tid];
            float sc = g_Sc[b*CC+tid], sc2 = g_Sc2[b*CC+tid];
            s += (float)MM * sp + (float)NN * sc;
            q += (float)MM * sp2 + 2.f * sp * sc + (float)NN * sc2;
        }
        float inv = 1.f / (float)PCNT;
        float mean = s * inv;
        float var  = q * inv - mean * mean;
        float a = g1[tid] * rsqrtf(var + EPS);
        sa1[tid] = a;
        sd1[tid] = b1[tid] - mean * a;
    }
    s2a[tid] = 0.f; q2a[tid] = 0.f;
    // W2 [o=256][k=128] -> sW2 (tf32-rounded)
    {
        const float4* wp = (const float4*)(W2 + tid*128);
        float* dst = sW2 + tid*PB_PW;
        #pragma unroll
        for (int u = 0; u < 32; u++) {
            float4 v = wp[u];
            dst[4*u+0] = to_tf32(v.x); dst[4*u+1] = to_tf32(v.y);
            dst[4*u+2] = to_tf32(v.z); dst[4*u+3] = to_tf32(v.w);
        }
    }
    __syncthreads();

    int s_q = tid & 15;                 // m-quad id for A build
    int c_hi = tid >> 4;                // 0..15

    for (int pair = blockIdx.x; pair < NPAIR; pair += gridDim.x) {
        int b = pair >> 10;
        // ---- build A = h1 [k=c][m'] (tf32), m' = bnl*64 + m ----
        #pragma unroll
        for (int i = 0; i < 8; i++) {
            int c = c_hi + 16*i;
            float a1v = sa1[c], d1v = sd1[c];
            float4 cv = *(const float4*)(g_CcT + (b*128 + c)*64 + 4*s_q);
            #pragma unroll
            for (int j = 0; j < 2; j++) {
                float pv = g_P[(pair*2 + j)*128 + c];
                float4 h;
                h.x = to_tf32(lrelu(fmaf(a1v, pv + cv.x, d1v)));
                h.y = to_tf32(lrelu(fmaf(a1v, pv + cv.y, d1v)));
                h.z = to_tf32(lrelu(fmaf(a1v, pv + cv.z, d1v)));
                h.w = to_tf32(lrelu(fmaf(a1v, pv + cv.w, d1v)));
                *(float4*)(sA + c*PB_PA + 4*s_q + 64*j) = h;
            }
        }
        __syncthreads();

        // ---- MMA: 64x64 per warp, K=128 ----
        float acc[4][8][4];
        #pragma unroll
        for (int mt = 0; mt < 4; mt++)
            #pragma unroll
            for (int nt = 0; nt < 8; nt++)
                #pragma unroll
                for (int e = 0; e < 4; e++) acc[mt][nt][e] = 0.f;

        #pragma unroll 4
        for (int ks = 0; ks < 16; ks++) {
            int k0 = ks * 8;
            uint32_t af[4][4];
            #pragma unroll
            for (int mt = 0; mt < 4; mt++) {
                const float* ap = sA + (k0 + t)*PB_PA + wm*64 + mt*16 + g;
                af[mt][0] = __float_as_uint(ap[0]);
                af[mt][1] = __float_as_uint(ap[8]);
                af[mt][2] = __float_as_uint(ap[4*PB_PA]);
                af[mt][3] = __float_as_uint(ap[4*PB_PA + 8]);
            }
            #pragma unroll
            for (int nt = 0; nt < 8; nt++) {
                const float* bp = sW2 + (wn*64 + nt*8 + g)*PB_PW + k0 + t;
                uint32_t b0 = __float_as_uint(bp[0]);
                uint32_t b1v = __float_as_uint(bp[4]);
                #pragma unroll
                for (int mt = 0; mt < 4; mt++)
                    mma_tf32(acc[mt][nt], af[mt][0], af[mt][1], af[mt][2], af[mt][3], b0, b1v);
            }
        }
        __syncthreads();   // sA consumed; next tile may rebuild

        // ---- epilogue: direct frag store to z2 [bn][m][o] + stats ----
        size_t zb = (size_t)(pair*2 + wm) * 16384;
        #pragma unroll
        for (int nt = 0; nt < 8; nt++) {
            int colb = wn*64 + nt*8 + 2*t;
            float s0 = 0.f, q0 = 0.f, s1 = 0.f, q1 = 0.f;
            #pragma unroll
            for (int mt = 0; mt < 4; mt++) {
                float* c = acc[mt][nt];
                int m = mt*16 + g;
                *(float2*)&g_z2[zb + (size_t)m*256 + colb]     = make_float2(c[0], c[1]);
                *(float2*)&g_z2[zb + (size_t)(m+8)*256 + colb] = make_float2(c[2], c[3]);
                s0 += c[0] + c[2]; q0 = fmaf(c[0], c[0], fmaf(c[2], c[2], q0));
                s1 += c[1] + c[3]; q1 = fmaf(c[1], c[1], fmaf(c[3], c[3], q1));
            }
            #pragma unroll
            for (int mk = 4; mk <= 16; mk <<= 1) {
                s0 += __shfl_xor_sync(0xFFFFFFFFu, s0, mk);
                q0 += __shfl_xor_sync(0xFFFFFFFFu, q0, mk);
                s1 += __shfl_xor_sync(0xFFFFFFFFu, s1, mk);
                q1 += __shfl_xor_sync(0xFFFFFFFFu, q1, mk);
            }
            if (g == 0) {
                atomicAdd(&s2a[colb],   s0); atomicAdd(&q2a[colb],   q0);
                atomicAdd(&s2a[colb+1], s1); atomicAdd(&q2a[colb+1], q1);
            }
        }
    }
    __syncthreads();
    atomicAdd(&g_s2[tid], s2a[tid]);
    atomicAdd(&g_q2[tid], q2a[tid]);
}

// =====================================================================
// K5: passC : z3 = h2 @ W3^T (N half h), max/min + bn3 stats
// smem floats: sW3 [128][260]=33280 | sA [m=128][132]=16896 | s3a/q3a 512
//              total 50688 floats = 202752 B
// sA row layout: k-cols 0..63 at +0, 64..127 at +68 (bank-safe frag loads)
// =====================================================================
#define PC_PW 260
#define PC_PA 132
#define SMEM_PC (50688*4)
__global__ __launch_bounds__(256, 1) void rn_passC_mma(const float* __restrict__ W3,
                                                       const float* __restrict__ g2,
                                                       const float* __restrict__ b2) {
    extern __shared__ float sm[];
    float* sW3 = sm;                 // [o][k] pitch 260 (K=256)
    float* sA  = sW3 + 128*PC_PW;    // [m][k-chunk] pitch 132
    float* s3a = sA + 128*PC_PA;     // 256
    float* q3a = s3a + 256;          // 256
    __shared__ float sa2[256], sd2[256];

    int tid = threadIdx.x, wid = tid >> 5, lane = tid & 31;
    int g = lane >> 2, t = lane & 3;
    int wm = wid >> 2, wn = wid & 3;  // warp tile 64(M) x 32(N)

    // inline bn2 finalize
    {
        float inv = 1.f / (float)PCNT;
        float mean = g_s2[tid] * inv;
        float var  = g_q2[tid] * inv - mean * mean;
        float a = g2[tid] * rsqrtf(var + EPS);
        sa2[tid] = a; sd2[tid] = b2[tid] - mean * a;
    }
    s3a[tid] = 0.f; q3a[tid] = 0.f;
    __syncthreads();

    int m_ = tid >> 1, half = tid & 1;           // A-build mapping
    int bn_off = m_ >> 6, mrow = m_ & 63;

    int curh = -1;
    for (int w = blockIdx.x; w < 2*NPAIR; w += gridDim.x) {
        int h = w >> 11, pair = w & (NPAIR - 1);     // h-major
        if (h != curh) {
            __syncthreads();
            // W3 half [o=128][k=256] -> sW3 (tf32)
            int o = tid >> 1, kh = (tid & 1) * 128;
            const float4* wp = (const float4*)(W3 + (size_t)(h*128 + o)*256 + kh);
            float* dst = sW3 + o*PC_PW + kh;
            #pragma unroll
            for (int u = 0; u < 32; u++) {
                float4 v = wp[u];
                dst[4*u+0] = to_tf32(v.x); dst[4*u+1] = to_tf32(v.y);
                dst[4*u+2] = to_tf32(v.z); dst[4*u+3] = to_tf32(v.w);
            }
            __syncthreads();
            curh = h;
        }

        float acc[4][4][4];
        #pragma unroll
        for (int mt = 0; mt < 4; mt++)
            #pragma unroll
            for (int nt = 0; nt < 4; nt++)
                #pragma unroll
                for (int e = 0; e < 4; e++) acc[mt][nt][e] = 0.f;

        #pragma unroll
        for (int kc = 0; kc < 2; kc++) {
            // ---- build A chunk: z2 [bn][m][o] -> bn2+lrelu -> tf32 [m][k] ----
            const float* src = g_z2 + (size_t)(pair*2 + bn_off)*16384
                             + (size_t)mrow*256 + kc*128 + half*64;
            float* dst = sA + m_*PC_PA + half*68;
            int kgb = kc*128 + half*64;
            #pragma unroll
            for (int i = 0; i < 16; i++) {
                int kg = kgb + 4*i;
                float4 v = *(const float4*)(src + 4*i);
                float4 hx;
                hx.x = to_tf32(lrelu(fmaf(sa2[kg+0], v.x, sd2[kg+0])));
                hx.y = to_tf32(lrelu(fmaf(sa2[kg+1], v.y, sd2[kg+1])));
                hx.z = to_tf32(lrelu(fmaf(sa2[kg+2], v.z, sd2[kg+2])));
                hx.w = to_tf32(lrelu(fmaf(sa2[kg+3], v.w, sd2[kg+3])));
                *(float4*)(dst + 4*i) = hx;
            }
            __syncthreads();
            // ---- MMA: 16 k-steps over this chunk ----
            #pragma unroll 4
            for (int ks = 0; ks < 16; ks++) {
                int k0 = ks * 8;
                int koff = (k0 < 64) ? k0 : k0 + 4;     // dual-offset layout
                uint32_t af[4][4];
                #pragma unroll
                for (int mt = 0; mt < 4; mt++) {
                    const float* ap = sA + (wm*64 + mt*16 + g)*PC_PA + koff + t;
                    af[mt][0] = __float_as_uint(ap[0]);
                    af[mt][1] = __float_as_uint(ap[8*PC_PA]);
                    af[mt][2] = __float_as_uint(ap[4]);
                    af[mt][3] = __float_as_uint(ap[8*PC_PA + 4]);
                }
                #pragma unroll
                for (int nt = 0; nt < 4; nt++) {
                    const float* bp = sW3 + (wn*32 + nt*8 + g)*PC_PW + kc*128 + k0 + t;
                    uint32_t b0 = __float_as_uint(bp[0]);
                    uint32_t b1v = __float_as_uint(bp[4]);
                    #pragma unroll
                    for (int mt = 0; mt < 4; mt++)
                        mma_tf32(acc[mt][nt], af[mt][0], af[mt][1], af[mt][2], af[mt][3], b0, b1v);
                }
            }
            __syncthreads();   // A consumed before next chunk overwrites
        }

        // ---- reduce over m from fragments: warp wm <-> bn = pair*2+wm ----
        #pragma unroll
        for (int nt = 0; nt < 4; nt++) {
            #pragma unroll
            for (int e = 0; e < 2; e++) {
                float mx = -3.402823466e38f, mn = 3.402823466e38f, s = 0.f, q = 0.f;
                #pragma unroll
                for (int mt = 0; mt < 4; mt++) {
                    float v0 = acc[mt][nt][e], v1 = acc[mt][nt][e+2];
                    mx = fmaxf(mx, fmaxf(v0, v1));
                    mn = fminf(mn, fminf(v0, v1));
                    s += v0 + v1;
                    q = fmaf(v0, v0, q); q = fmaf(v1, v1, q);
                }
                #pragma unroll
                for (int mk = 4; mk <= 16; mk <<= 1) {
                    mx = fmaxf(mx, __shfl_xor_sync(0xFFFFFFFFu, mx, mk));
                    mn = fminf(mn, __shfl_xor_sync(0xFFFFFFFFu, mn, mk));
                    s += __shfl_xor_sync(0xFFFFFFFFu, s, mk);
                    q += __shfl_xor_sync(0xFFFFFFFFu, q, mk);
                }
                if (lane < 4) {
                    int gc = h*128 + wn*32 + nt*8 + 2*lane + e;
                    int bn = pair*2 + wm;
                    g_zmax[bn*C2 + gc] = mx;
                    g_zmin[bn*C2 + gc] = mn;
                    atomicAdd(&s3a[gc], s);
                    atomicAdd(&q3a[gc], q);
                }
            }
        }
    }
    __syncthreads();
    atomicAdd(&g_s3[tid], s3a[tid]);
    atomicAdd(&g_q3[tid], q3a[tid]);
}

// ---------------- bn3 finalize ----------------
__global__ void rn_bn3fin(const float* __restrict__ g3, const float* __restrict__ b3) {
    int o = threadIdx.x;
    float inv = 1.f / (float)PCNT;
    float mean = g_s3[o] * inv;
    float var  = g_q3[o] * inv - mean * mean;
    float a = g3[o] * rsqrtf(var + EPS);
    g_a3[o] = a; g_d3[o] = b3[o] - mean * a;
}

// ---------------- fc1 ----------------
__global__ void rn_fc1(const float* __restrict__ fw, const float* __restrict__ fb) {
    __shared__ float sh[C2];
    int r = blockIdx.x, o = threadIdx.x;              // 128 threads
    for (int c = o; c < C2; c += 128) {
        float a3 = g_a3[c], d3 = g_d3[c];
        float z = (a3 >= 0.f) ? g_zmax[r*C2 + c] : g_zmin[r*C2 + c];
        float v = fmaf(a3, z, d3);
        sh[c] = (v >= 0.f) ? v : SLOPE * v;
    }
    __syncthreads();
    const float* wr = fw + o*C2;
    float acc = fb[o];
    #pragma unroll
    for (int c = 0; c < C2; c += 4) {
        float4 wv = *(const float4*)(wr + c);
        acc = fmaf(wv.x, sh[c+0], acc); acc = fmaf(wv.y, sh[c+1], acc);
        acc = fmaf(wv.z, sh[c+2], acc); acc = fmaf(wv.w, sh[c+3], acc);
    }
    g_z4[r*128 + o] = acc;
    atomicAdd(&g_s4[o], acc);
    atomicAdd(&g_q4[o], acc*acc);
}
__global__ void rn_bn4fin(const float* __restrict__ g4, const float* __restrict__ b4) {
    int o = threadIdx.x;
    float inv = 1.f / (float)BNR;
    float mean = g_s4[o] * inv;
    float var  = g_q4[o] * inv - mean * mean;
    float a = g4[o] * rsqrtf(var + EPS);
    g_a4[o] = a; g_d4[o] = b4[o] - mean * a;
}

// ---------------- fc2 ----------------
__global__ void rn_fc2(const float* __restrict__ fw, const float* __restrict__ fb) {
    __shared__ float sh[128];
    int r = blockIdx.x, t = threadIdx.x;
    float v = fmaf(g_a4[t], g_z4[r*128 + t], g_d4[t]);
    sh[t] = fmaxf(v, 0.f);
    __syncthreads();
    if (t < OUTC) {
        const float* wr = fw + t*128;
        float acc = fb[t];
        #pragma unroll
        for (int c = 0; c < 128; c += 4) {
            float4 wv = *(const float4*)(wr + c);
            acc = fmaf(wv.x, sh[c+0], acc); acc = fmaf(wv.y, sh[c+1], acc);
            acc = fmaf(wv.z, sh[c+2], acc); acc = fmaf(wv.w, sh[c+3], acc);
        }
        g_z5[r*OUTC + t] = acc;
        atomicAdd(&g_s5[t], acc);
        atomicAdd(&g_q5[t], acc*acc);
    }
}
__global__ void rn_bn5fin(const float* __restrict__ g5, const float* __restrict__ b5) {
    int o = threadIdx.x;
    float inv = 1.f / (float)BNR;
    float mean = g_s5[o] * inv;
    float var  = g_q5[o] * inv - mean * mean;
    float a = g5[o] * rsqrtf(var + EPS);
    g_a5[o] = a; g_d5[o] = b5[o] - mean * a;
}

// ---------------- output ----------------
__global__ void rn_out(float* __restrict__ out) {
    int i = blockIdx.x * 256 + threadIdx.x;           // 262144 total
    int o = i & (OUTC - 1);
    float v = fmaf(g_a5[o], g_z5[i], g_d5[o]);
    out[i] = fmaxf(v, 0.f);
}

// ---------------- launch ----------------
extern "C" void kernel_launch(void* const* d_in, const int* in_sizes, int n_in,
                              void* d_out, int out_size) {
    const float* pf   = (const float*)d_in[0];
    const float* cf   = (const float*)d_in[1];
    const float* W1   = (const float*)d_in[2];
    const float* g1   = (const float*)d_in[3];
    const float* b1   = (const float*)d_in[4];
    const float* W2   = (const float*)d_in[5];
    const float* g2   = (const float*)d_in[6];
    const float* b2   = (const float*)d_in[7];
    const float* W3   = (const float*)d_in[8];
    const float* g3   = (const float*)d_in[9];
    const float* b3   = (const float*)d_in[10];
    const float* fc1w = (const float*)d_in[11];
    const float* fc1b = (const float*)d_in[12];
    const float* g4   = (const float*)d_in[13];
    const float* b4   = (const float*)d_in[14];
    const float* fc2w = (const float*)d_in[15];
    const float* fc2b = (const float*)d_in[16];
    const float* g5   = (const float*)d_in[17];
    const float* b5   = (const float*)d_in[18];

    cudaFuncSetAttribute(rn_passB_mma, cudaFuncAttributeMaxDynamicSharedMemorySize, SMEM_PB);
    cudaFuncSetAttribute(rn_passC_mma, cudaFuncAttributeMaxDynamicSharedMemorySize, SMEM_PC);

    rn_prep  <<<1, 256>>>();                              // launch 0
    rn_pc    <<<BNR + BB*MM, 128>>>(pf, cf, W1);          // launch 1 (also CcT)
    rn_bn1a  <<<32, 128>>>();                             // launch 2
    rn_passB_mma <<<148, 256, SMEM_PB>>>(W2, g1, b1);     // launch 3  <- ncu window
    rn_passC_mma <<<148, 256, SMEM_PC>>>(W3, g2, b2);     // launch 4
    rn_bn3fin<<<1, 256>>>(g3, b3);
    rn_fc1   <<<BNR, 128>>>(fc1w, fc1b);
    rn_bn4fin<<<1, 128>>>(g4, b4);
    rn_fc2   <<<BNR, 128>>>(fc2w, fc2b);
    rn_bn5fin<<<1, 64>>>(g5, b5);
    rn_out   <<<PCNT/256, 256>>>((float*)d_out);
}